// round 4
// baseline (speedup 1.0000x reference)
#include <cuda_runtime.h>
#include <cuda_bf16.h>
#include <math.h>
#include <stdint.h>

// ---------------- problem constants ----------------
#define Bz   16
#define Kk   2000
#define Qq   256
#define Dd   1024
#define AD   1024
#define Hh   4
#define DK   256
#define WW   8

#define EPI_BIAS    0
#define EPI_SIGMOID 1
#define EPI_SCALE   2

#define OUT_F32      0
#define OUT_PLANES   1
#define OUT_PLANES_T 2

typedef __nv_bfloat16  bf16;
typedef __nv_bfloat162 bf162;

// ---------------- scratch (static device memory) ----------------
// fp32 intermediates
__device__ float g_P [Bz * Hh * Qq * Kk];
__device__ float g_CP[Bz * Hh * Qq * Kk];
__device__ float g_AL[Bz * Hh * Qq * Kk];
__device__ float g_E [Bz * Hh * Qq * Kk];

// bf16 hi/lo planes
__device__ bf16 g_KEYh[Bz * Kk * Dd], g_KEYl[Bz * Kk * Dd];
__device__ bf16 g_VALh[Bz * Kk * Dd], g_VALl[Bz * Kk * Dd];
__device__ bf16 g_QRYh[Bz * Qq * Dd], g_QRYl[Bz * Qq * Dd];

__device__ bf16 g_WKMAh[Dd * AD], g_WKMAl[Dd * AD];
__device__ bf16 g_WQMAh[Dd * AD], g_WQMAl[Dd * AD];
__device__ bf16 g_WKCAh[Dd * AD], g_WKCAl[Dd * AD];
__device__ bf16 g_WQCAh[Dd * AD], g_WQCAl[Dd * AD];
__device__ bf16 g_WVh  [Dd * AD], g_WVl  [Dd * AD];
__device__ bf16 g_WOh  [AD * Dd], g_WOl  [AD * Dd];

__device__ bf16 g_KMAh[Bz * Kk * AD], g_KMAl[Bz * Kk * AD];
__device__ bf16 g_KCAh[Bz * Kk * AD], g_KCAl[Bz * Kk * AD];
__device__ bf16 g_QMAh[Bz * Qq * AD], g_QMAl[Bz * Qq * AD];
__device__ bf16 g_QCAh[Bz * Qq * AD], g_QCAl[Bz * Qq * AD];
__device__ bf16 g_VPTh[Bz * AD * Kk], g_VPTl[Bz * AD * Kk];   // transposed [b][(h,d)][kk]
__device__ bf16 g_BTh [Bz * Hh * Qq * Kk], g_BTl [Bz * Hh * Qq * Kk];
__device__ bf16 g_CVh [Bz * Qq * AD], g_CVl [Bz * Qq * AD];

// ---------------- helpers ----------------
__device__ __forceinline__ void splitw(float x, float y, bf162& h, bf162& l)
{
    h = __floats2bfloat162_rn(x, y);
    float2 hf = __bfloat1622float2(h);
    l = __floats2bfloat162_rn(x - hf.x, y - hf.y);
}

__device__ __forceinline__ void mma_bf16(float (&d)[4],
                                         const unsigned (&a)[4],
                                         const unsigned (&b)[2])
{
    asm volatile(
        "mma.sync.aligned.m16n8k16.row.col.f32.bf16.bf16.f32 "
        "{%0,%1,%2,%3}, {%4,%5,%6,%7}, {%8,%9}, {%0,%1,%2,%3};\n"
        : "+f"(d[0]), "+f"(d[1]), "+f"(d[2]), "+f"(d[3])
        : "r"(a[0]), "r"(a[1]), "r"(a[2]), "r"(a[3]),
          "r"(b[0]), "r"(b[1]));
}

__device__ __forceinline__ void cpa16(uint32_t dst, const bf16* src, bool v)
{
    int sz = v ? 16 : 0;
    asm volatile("cp.async.cg.shared.global [%0], [%1], 16, %2;\n"
                 :: "r"(dst), "l"(src), "r"(sz));
}

#define LDMX4(r0, r1, r2, r3, addr)                                          \
    asm volatile("ldmatrix.sync.aligned.m8n8.x4.shared.b16 {%0,%1,%2,%3}, [%4];" \
                 : "=r"(r0), "=r"(r1), "=r"(r2), "=r"(r3) : "r"(addr))

// ---------------- pre-split bf16 tensor GEMM ----------------
// A planes: [m][k] row-major (lda).  B planes: [n][k] row-major (ldb).
// 128x128x32 tile, 8 warps (warp tile 64x32), cp.async 2-stage.
// Smem per stage: Ah,Al,Bh,Bl each 128 rows * 80B = 10240B -> 40960B; 2 stages.
template<int EPI, int OUTM>
__global__ void __launch_bounds__(256, 2)
bgemm(const bf16* __restrict__ Ahg, const bf16* __restrict__ Alg,
      const bf16* __restrict__ Bhg, const bf16* __restrict__ Blg,
      const float* __restrict__ bias,
      float* __restrict__ C, bf16* __restrict__ Ch, bf16* __restrict__ Cl,
      int M, int N, int Kd, int lda, int ldb, int ldc,
      int Hdiv,
      long long sAb, long long sAh,
      long long sBb, long long sBh,
      long long sCb, long long sCh,
      float escale, const float* __restrict__ rptr, int rdiv)
{
    extern __shared__ char smem_raw[];
    const uint32_t smem0 = (uint32_t)__cvta_generic_to_shared(smem_raw);

    {
        int z  = blockIdx.z;
        int zb = z / Hdiv;
        int zh = z - zb * Hdiv;
        Ahg += (long long)zb * sAb + (long long)zh * sAh;
        Alg += (long long)zb * sAb + (long long)zh * sAh;
        Bhg += (long long)zb * sBb + (long long)zh * sBh;
        Blg += (long long)zb * sBb + (long long)zh * sBh;
        long long co = (long long)zb * sCb + (long long)zh * sCh;
        if (OUTM == OUT_F32) C += co; else { Ch += co; Cl += co; }
    }

    const int tid  = threadIdx.x;
    const int lane = tid & 31;
    const int wid  = tid >> 5;
    const int wm   = wid & 1;        // 2 warps over M (64 each)
    const int wn   = wid >> 1;       // 4 warps over N (32 each)
    const int gid  = lane >> 2;
    const int tig  = lane & 3;
    const int m0   = blockIdx.y * 128;
    const int n0   = blockIdx.x * 128;

    const int arow = (wm * 64 + (lane & 15)) * 80 + ((lane >> 4) << 4);
    const int brow = (wn * 32 + (lane & 15)) * 80 + ((lane >> 4) << 4);

    float acc[4][4][4];
#pragma unroll
    for (int mi = 0; mi < 4; mi++)
#pragma unroll
        for (int ni = 0; ni < 4; ni++)
#pragma unroll
            for (int e = 0; e < 4; e++) acc[mi][ni][e] = 0.f;

    const int nk = (Kd + 31) >> 5;

    auto loadTile = [&](int kt, int s) {
        uint32_t base = smem0 + s * 40960;
#pragma unroll
        for (int it = 0; it < 2; ++it) {
            int idx = tid + it * 256;
            int row = idx & 127;
            int c   = idx >> 7;
            uint32_t so = row * 80 + c * 16;
            int kg = kt * 32 + c * 8;
            long long ga = (long long)(m0 + row) * lda + kg;
            bool v = kg < Kd;                       // A rows always valid (M % 128 == 0)
            cpa16(base + so,         Ahg + ga, v);
            cpa16(base + 10240 + so, Alg + ga, v);
        }
#pragma unroll
        for (int it = 0; it < 2; ++it) {
            int idx = tid + it * 256;
            int row = idx & 127;
            int c   = idx >> 7;
            uint32_t so = row * 80 + c * 16;
            int kg = kt * 32 + c * 8;
            long long gb = (long long)(n0 + row) * ldb + kg;
            bool v = (n0 + row < N) && (kg < Kd);
            cpa16(base + 20480 + so, Bhg + gb, v);
            cpa16(base + 30720 + so, Blg + gb, v);
        }
    };

    loadTile(0, 0);
    asm volatile("cp.async.commit_group;\n" ::: "memory");
    if (nk > 1) loadTile(1, 1);
    asm volatile("cp.async.commit_group;\n" ::: "memory");

    for (int kt = 0; kt < nk; ++kt) {
        if (kt + 1 < nk) asm volatile("cp.async.wait_group 1;\n" ::: "memory");
        else             asm volatile("cp.async.wait_group 0;\n" ::: "memory");
        __syncthreads();

        const uint32_t base = smem0 + (kt & 1) * 40960;
#pragma unroll
        for (int ks = 0; ks < 2; ++ks) {
            unsigned bh[4][2], bl[4][2];
            {
                unsigned r0, r1, r2, r3;
                LDMX4(r0, r1, r2, r3, base + 20480 + brow + ks * 32);
                bh[0][0] = r0; bh[1][0] = r1; bh[0][1] = r2; bh[1][1] = r3;
                LDMX4(r0, r1, r2, r3, base + 20480 + brow + 1280 + ks * 32);
                bh[2][0] = r0; bh[3][0] = r1; bh[2][1] = r2; bh[3][1] = r3;
                LDMX4(r0, r1, r2, r3, base + 30720 + brow + ks * 32);
                bl[0][0] = r0; bl[1][0] = r1; bl[0][1] = r2; bl[1][1] = r3;
                LDMX4(r0, r1, r2, r3, base + 30720 + brow + 1280 + ks * 32);
                bl[2][0] = r0; bl[3][0] = r1; bl[2][1] = r2; bl[3][1] = r3;
            }
#pragma unroll
            for (int mp = 0; mp < 2; ++mp) {
                unsigned ah[2][4], al[2][4];
                LDMX4(ah[0][0], ah[0][1], ah[0][2], ah[0][3],
                      base + arow + (mp * 2) * 1280 + ks * 32);
                LDMX4(ah[1][0], ah[1][1], ah[1][2], ah[1][3],
                      base + arow + (mp * 2 + 1) * 1280 + ks * 32);
                LDMX4(al[0][0], al[0][1], al[0][2], al[0][3],
                      base + 10240 + arow + (mp * 2) * 1280 + ks * 32);
                LDMX4(al[1][0], al[1][1], al[1][2], al[1][3],
                      base + 10240 + arow + (mp * 2 + 1) * 1280 + ks * 32);
#pragma unroll
                for (int q = 0; q < 2; ++q)
#pragma unroll
                    for (int ni = 0; ni < 4; ++ni)
                        mma_bf16(acc[mp * 2 + q][ni], ah[q], bh[ni]);
#pragma unroll
                for (int q = 0; q < 2; ++q)
#pragma unroll
                    for (int ni = 0; ni < 4; ++ni)
                        mma_bf16(acc[mp * 2 + q][ni], ah[q], bl[ni]);
#pragma unroll
                for (int q = 0; q < 2; ++q)
#pragma unroll
                    for (int ni = 0; ni < 4; ++ni)
                        mma_bf16(acc[mp * 2 + q][ni], al[q], bh[ni]);
            }
        }
        __syncthreads();
        if (kt + 2 < nk) loadTile(kt + 2, kt & 1);
        asm volatile("cp.async.commit_group;\n" ::: "memory");
    }

    // ---------------- epilogue ----------------
    float rv = 0.f;
    if (EPI == EPI_SIGMOID && rptr != nullptr) rv = rptr[0];

    auto epi = [&](float v, float b) -> float {
        if (EPI == EPI_BIAS)    return v + b;
        if (EPI == EPI_SIGMOID) { v = v * escale + rv; return 1.f / (1.f + __expf(-v)); }
        return v * escale;
    };

#pragma unroll
    for (int mi = 0; mi < 4; mi++) {
#pragma unroll
        for (int ni = 0; ni < 4; ni++) {
            int r  = m0 + wm * 64 + mi * 16 + gid;
            int cc = n0 + wn * 32 + ni * 8 + 2 * tig;
            if (cc >= N) continue;  // N even
            float bx = 0.f, by = 0.f;
            if (EPI == EPI_BIAS && bias != nullptr) { bx = bias[cc]; by = bias[cc + 1]; }
            float v0 = epi(acc[mi][ni][0], bx);
            float v1 = epi(acc[mi][ni][1], by);
            float v2 = epi(acc[mi][ni][2], bx);
            float v3 = epi(acc[mi][ni][3], by);
            if (OUTM == OUT_F32) {
                *reinterpret_cast<float2*>(C + (long long)r * ldc + cc) =
                    make_float2(v0, v1);
                *reinterpret_cast<float2*>(C + (long long)(r + 8) * ldc + cc) =
                    make_float2(v2, v3);
            } else if (OUTM == OUT_PLANES) {
                bf162 h, l;
                splitw(v0, v1, h, l);
                *reinterpret_cast<bf162*>(Ch + (long long)r * ldc + cc) = h;
                *reinterpret_cast<bf162*>(Cl + (long long)r * ldc + cc) = l;
                splitw(v2, v3, h, l);
                *reinterpret_cast<bf162*>(Ch + (long long)(r + 8) * ldc + cc) = h;
                *reinterpret_cast<bf162*>(Cl + (long long)(r + 8) * ldc + cc) = l;
            } else {  // OUT_PLANES_T: out[(b*N + n)][kk], b = r/rdiv, kk = r%rdiv
                float vv[2][2] = {{v0, v1}, {v2, v3}};
#pragma unroll
                for (int gq = 0; gq < 2; ++gq) {
                    int rr = r + gq * 8;
                    long long bb = rr / rdiv;
                    int kx = rr - (int)bb * rdiv;
                    long long o = (bb * (long long)N + cc) * (long long)rdiv + kx;
                    bf16 h0 = __float2bfloat16_rn(vv[gq][0]);
                    bf16 h1 = __float2bfloat16_rn(vv[gq][1]);
                    Ch[o]        = h0;
                    Ch[o + rdiv] = h1;
                    Cl[o]        = __float2bfloat16_rn(vv[gq][0] - __bfloat162float(h0));
                    Cl[o + rdiv] = __float2bfloat16_rn(vv[gq][1] - __bfloat162float(h1));
                }
            }
        }
    }
}

// ---------------- preprocessing: split fp32 -> bf16 hi/lo planes -------------
__global__ void __launch_bounds__(256) split_kernel(const float* __restrict__ X,
                                                    bf16* __restrict__ H,
                                                    bf16* __restrict__ L, int n)
{
    int i = (blockIdx.x * 256 + threadIdx.x) * 4;
    if (i >= n) return;
    float4 v = *reinterpret_cast<const float4*>(X + i);
    bf162 h0, l0, h1, l1;
    splitw(v.x, v.y, h0, l0);
    splitw(v.z, v.w, h1, l1);
    *reinterpret_cast<bf162*>(H + i)     = h0;
    *reinterpret_cast<bf162*>(H + i + 2) = h1;
    *reinterpret_cast<bf162*>(L + i)     = l0;
    *reinterpret_cast<bf162*>(L + i + 2) = l1;
}

// transpose W[k][n] (1024x1024 fp32) -> planes [n][k]
__global__ void __launch_bounds__(256) transpose_split(const float* __restrict__ W,
                                                       bf16* __restrict__ Th,
                                                       bf16* __restrict__ Tl)
{
    __shared__ float t[32][33];
    int tx = threadIdx.x, ty = threadIdx.y;   // 32 x 8
    int bk = blockIdx.y * 32, bn = blockIdx.x * 32;
#pragma unroll
    for (int i = 0; i < 4; i++)
        t[ty + i * 8][tx] = W[(long long)(bk + ty + i * 8) * 1024 + bn + tx];
    __syncthreads();
#pragma unroll
    for (int i = 0; i < 4; i++) {
        int n = bn + ty + i * 8;
        int k = bk + tx;
        float v = t[tx][ty + i * 8];
        bf16 h = __float2bfloat16_rn(v);
        Th[(long long)n * 1024 + k] = h;
        Tl[(long long)n * 1024 + k] = __float2bfloat16_rn(v - __bfloat162float(h));
    }
}

// ---------------- cp = exclusive cumprod of clip(1-p) ------------------------
__global__ void __launch_bounds__(256) cp_kernel(const float* __restrict__ P,
                                                 float* __restrict__ CP)
{
    __shared__ float ws[8];
    long long base = (long long)blockIdx.x * Kk;
    int tid  = threadIdx.x;
    int k0   = tid * 8;
    bool act = (k0 < Kk);
    int lane = tid & 31;
    int w    = tid >> 5;

    float l[8];
    float t = 1.f;
    if (act) {
        float4 p0 = *reinterpret_cast<const float4*>(P + base + k0);
        float4 p1 = *reinterpret_cast<const float4*>(P + base + k0 + 4);
        l[0] = p0.x; l[1] = p0.y; l[2] = p0.z; l[3] = p0.w;
        l[4] = p1.x; l[5] = p1.y; l[6] = p1.z; l[7] = p1.w;
#pragma unroll
        for (int j = 0; j < 8; j++) {
            l[j] = fminf(fmaxf(1.f - l[j], 1e-6f), 1.f);
            t *= l[j];
        }
    } else {
#pragma unroll
        for (int j = 0; j < 8; j++) l[j] = 1.f;
    }

    float x = t;
#pragma unroll
    for (int d = 1; d < 32; d <<= 1) {
        float y = __shfl_up_sync(0xffffffffu, x, d);
        if (lane >= d) x *= y;
    }
    float exw = __shfl_up_sync(0xffffffffu, x, 1);
    if (lane == 0) exw = 1.f;
    if (lane == 31) ws[w] = x;
    __syncthreads();
    if (w == 0 && lane < 8) {
        float v = ws[lane];
        float xx = v;
#pragma unroll
        for (int d = 1; d < 8; d <<= 1) {
            float y = __shfl_up_sync(0x000000ffu, xx, d);
            if (lane >= d) xx *= y;
        }
        float ex = __shfl_up_sync(0x000000ffu, xx, 1);
        if (lane == 0) ex = 1.f;
        ws[lane] = ex;
    }
    __syncthreads();

    if (act) {
        float run = ws[w] * exw;
        float o[8];
#pragma unroll
        for (int j = 0; j < 8; j++) { o[j] = run; run *= l[j]; }
        *reinterpret_cast<float4*>(CP + base + k0)     = make_float4(o[0], o[1], o[2], o[3]);
        *reinterpret_cast<float4*>(CP + base + k0 + 4) = make_float4(o[4], o[5], o[6], o[7]);
    }
}

// ---------------- alpha recurrence (sequential over Q) ----------------------
__global__ void __launch_bounds__(512) alpha_kernel(
    const float* __restrict__ P, const float* __restrict__ CP,
    const float* __restrict__ awp, float* __restrict__ AL)
{
    __shared__ float ws[2][16];
    const int bh   = blockIdx.x;
    const int tid  = threadIdx.x;
    const int lane = tid & 31;
    const int w    = tid >> 5;
    const int k0   = tid * 4;
    const bool act = (k0 < Kk);

    float aw[4] = {0.f, 0.f, 0.f, 0.f};
    if (act) {
        float4 v = *reinterpret_cast<const float4*>(awp + (long long)bh * Kk + k0);
        aw[0] = v.x; aw[1] = v.y; aw[2] = v.z; aw[3] = v.w;
    }

    const long long rbase = (long long)bh * Qq * Kk;

    float p[4] = {0, 0, 0, 0}, c[4] = {0, 0, 0, 0};
    if (act) {
        float4 pv = *reinterpret_cast<const float4*>(P + rbase + k0);
        float4 cv = *reinterpret_cast<const float4*>(CP + rbase + k0);
        p[0] = pv.x; p[1] = pv.y; p[2] = pv.z; p[3] = pv.w;
        c[0] = cv.x; c[1] = cv.y; c[2] = cv.z; c[3] = cv.w;
    }

    for (int i = 0; i < Qq; i++) {
        float np[4] = {0, 0, 0, 0}, nc[4] = {0, 0, 0, 0};
        if (act && i + 1 < Qq) {
            long long b = rbase + (long long)(i + 1) * Kk;
            float4 pv = *reinterpret_cast<const float4*>(P + b + k0);
            float4 cv = *reinterpret_cast<const float4*>(CP + b + k0);
            np[0] = pv.x; np[1] = pv.y; np[2] = pv.z; np[3] = pv.w;
            nc[0] = cv.x; nc[1] = cv.y; nc[2] = cv.z; nc[3] = cv.w;
        }
        float t[4];
#pragma unroll
        for (int j = 0; j < 4; j++) {
            float d = fminf(fmaxf(c[j], 1e-6f), 1.f);
            t[j] = __fdividef(aw[j], d);
        }
        float s = (t[0] + t[1]) + (t[2] + t[3]);

        int buf = i & 1;
        float x = s;
#pragma unroll
        for (int d = 1; d < 32; d <<= 1) {
            float y = __shfl_up_sync(0xffffffffu, x, d);
            if (lane >= d) x += y;
        }
        if (lane == 31) ws[buf][w] = x;
        __syncthreads();
        if (w == 0 && lane < 16) {
            float wv = ws[buf][lane];
            float xx = wv;
#pragma unroll
            for (int d = 1; d < 16; d <<= 1) {
                float y = __shfl_up_sync(0x0000ffffu, xx, d);
                if (lane >= d) xx += y;
            }
            ws[buf][lane] = xx - wv;
        }
        __syncthreads();
        float excl = ws[buf][w] + (x - s);

        float o0 = excl + t[0];
        float o1 = o0 + t[1];
        float o2 = o1 + t[2];
        float o3 = o2 + t[3];
        aw[0] = p[0] * c[0] * o0;
        aw[1] = p[1] * c[1] * o1;
        aw[2] = p[2] * c[2] * o2;
        aw[3] = p[3] * c[3] * o3;
        if (act)
            *reinterpret_cast<float4*>(AL + rbase + (long long)i * Kk + k0) =
                make_float4(aw[0], aw[1], aw[2], aw[3]);
#pragma unroll
        for (int j = 0; j < 4; j++) { p[j] = np[j]; c[j] = nc[j]; }
    }
}

// ---------------- beta: windowed weights; writes bf16 planes ----------------
__global__ void __launch_bounds__(256) beta_kernel(
    const float* __restrict__ E, const float* __restrict__ AL,
    bf16* __restrict__ BTh, bf16* __restrict__ BTl)
{
    __shared__ float sse[2048];
    __shared__ float gg[2048];
    __shared__ float red[8];
    long long base = (long long)blockIdx.x * Kk;
    int tid  = threadIdx.x;
    int k0   = tid * 8;
    bool act = (k0 < Kk);

    float ev[8];
    float mx = -3.4e38f;
    if (act) {
        float4 e0 = *reinterpret_cast<const float4*>(E + base + k0);
        float4 e1 = *reinterpret_cast<const float4*>(E + base + k0 + 4);
        ev[0] = e0.x; ev[1] = e0.y; ev[2] = e0.z; ev[3] = e0.w;
        ev[4] = e1.x; ev[5] = e1.y; ev[6] = e1.z; ev[7] = e1.w;
#pragma unroll
        for (int j = 0; j < 8; j++) mx = fmaxf(mx, ev[j]);
    }
#pragma unroll
    for (int d = 16; d; d >>= 1) mx = fmaxf(mx, __shfl_xor_sync(0xffffffffu, mx, d));
    if ((tid & 31) == 0) red[tid >> 5] = mx;
    __syncthreads();
    if (tid == 0) {
        float m = red[0];
#pragma unroll
        for (int i = 1; i < 8; i++) m = fmaxf(m, red[i]);
        red[0] = m;
    }
    __syncthreads();
    mx = red[0];

    float se[8];
#pragma unroll
    for (int j = 0; j < 8; j++)
        se[j] = act ? fmaxf(__expf(ev[j] - mx), 1e-5f) : 0.f;
    *reinterpret_cast<float4*>(&sse[k0])     = make_float4(se[0], se[1], se[2], se[3]);
    *reinterpret_cast<float4*>(&sse[k0 + 4]) = make_float4(se[4], se[5], se[6], se[7]);
    __syncthreads();

    float g[8];
    if (act) {
        float prev7[7];
#pragma unroll
        for (int d = 0; d < 7; d++) {
            int idx = k0 - 7 + d;
            prev7[d] = (idx >= 0) ? sse[idx] : 0.f;
        }
        float dn[8];
        float psum = prev7[0] + prev7[1] + prev7[2] + prev7[3]
                   + prev7[4] + prev7[5] + prev7[6];
        dn[0] = se[0] + psum;
#pragma unroll
        for (int j = 1; j < 8; j++)
            dn[j] = dn[j - 1] + se[j] - prev7[j - 1];

        float4 a0 = *reinterpret_cast<const float4*>(AL + base + k0);
        float4 a1 = *reinterpret_cast<const float4*>(AL + base + k0 + 4);
        float al[8] = {a0.x, a0.y, a0.z, a0.w, a1.x, a1.y, a1.z, a1.w};
#pragma unroll
        for (int j = 0; j < 8; j++)
            g[j] = __fdividef(al[j], dn[j]);
    } else {
#pragma unroll
        for (int j = 0; j < 8; j++) g[j] = 0.f;
    }
    *reinterpret_cast<float4*>(&gg[k0])     = make_float4(g[0], g[1], g[2], g[3]);
    *reinterpret_cast<float4*>(&gg[k0 + 4]) = make_float4(g[4], g[5], g[6], g[7]);
    __syncthreads();

    if (act) {
        float nxt7[7];
#pragma unroll
        for (int d = 0; d < 7; d++) {
            int idx = k0 + 8 + d;
            nxt7[d] = (idx < 2048) ? gg[idx] : 0.f;
        }
        float fw[8];
        fw[7] = g[7] + nxt7[0] + nxt7[1] + nxt7[2] + nxt7[3]
                     + nxt7[4] + nxt7[5] + nxt7[6];
#pragma unroll
        for (int j = 6; j >= 0; j--)
            fw[j] = fw[j + 1] + g[j] - nxt7[j];

        float o[8];
#pragma unroll
        for (int j = 0; j < 8; j++) o[j] = se[j] * fw[j];
#pragma unroll
        for (int j = 0; j < 4; j++) {
            bf162 h, l;
            splitw(o[2 * j], o[2 * j + 1], h, l);
            reinterpret_cast<bf162*>(BTh + base + k0)[j] = h;
            reinterpret_cast<bf162*>(BTl + base + k0)[j] = l;
        }
    }
}

// ---------------- host driver ------------------------------------------------
extern "C" void kernel_launch(void* const* d_in, const int* in_sizes, int n_in,
                              void* d_out, int out_size)
{
    (void)in_sizes; (void)n_in; (void)out_size;

    const float* key     = (const float*)d_in[0];
    const float* value   = (const float*)d_in[1];
    const float* query   = (const float*)d_in[2];
    const float* aw_prev = (const float*)d_in[4];
    const float* Wk_ma   = (const float*)d_in[5];
    const float* bk_ma   = (const float*)d_in[6];
    const float* Wq_ma   = (const float*)d_in[7];
    const float* bq_ma   = (const float*)d_in[8];
    const float* r       = (const float*)d_in[9];
    const float* Wk_ca   = (const float*)d_in[10];
    const float* bk_ca   = (const float*)d_in[11];
    const float* Wq_ca   = (const float*)d_in[12];
    const float* bq_ca   = (const float*)d_in[13];
    const float* Wv      = (const float*)d_in[14];
    const float* bv      = (const float*)d_in[15];
    const float* Wo      = (const float*)d_in[16];
    const float* bo      = (const float*)d_in[17];
    float* out = (float*)d_out;

    float *P, *CP, *AL, *E;
    cudaGetSymbolAddress((void**)&P,  g_P);
    cudaGetSymbolAddress((void**)&CP, g_CP);
    cudaGetSymbolAddress((void**)&AL, g_AL);
    cudaGetSymbolAddress((void**)&E,  g_E);

    bf16 *KEYh, *KEYl, *VALh, *VALl, *QRYh, *QRYl;
    bf16 *WKMAh, *WKMAl, *WQMAh, *WQMAl, *WKCAh, *WKCAl, *WQCAh, *WQCAl;
    bf16 *WVh, *WVl, *WOh, *WOl;
    bf16 *KMAh, *KMAl, *KCAh, *KCAl, *QMAh, *QMAl, *QCAh, *QCAl;
    bf16 *VPTh, *VPTl, *BThp, *BTlp, *CVh, *CVl;
    cudaGetSymbolAddress((void**)&KEYh, g_KEYh);  cudaGetSymbolAddress((void**)&KEYl, g_KEYl);
    cudaGetSymbolAddress((void**)&VALh, g_VALh);  cudaGetSymbolAddress((void**)&VALl, g_VALl);
    cudaGetSymbolAddress((void**)&QRYh, g_QRYh);  cudaGetSymbolAddress((void**)&QRYl, g_QRYl);
    cudaGetSymbolAddress((void**)&WKMAh, g_WKMAh); cudaGetSymbolAddress((void**)&WKMAl, g_WKMAl);
    cudaGetSymbolAddress((void**)&WQMAh, g_WQMAh); cudaGetSymbolAddress((void**)&WQMAl, g_WQMAl);
    cudaGetSymbolAddress((void**)&WKCAh, g_WKCAh); cudaGetSymbolAddress((void**)&WKCAl, g_WKCAl);
    cudaGetSymbolAddress((void**)&WQCAh, g_WQCAh); cudaGetSymbolAddress((void**)&WQCAl, g_WQCAl);
    cudaGetSymbolAddress((void**)&WVh, g_WVh);    cudaGetSymbolAddress((void**)&WVl, g_WVl);
    cudaGetSymbolAddress((void**)&WOh, g_WOh);    cudaGetSymbolAddress((void**)&WOl, g_WOl);
    cudaGetSymbolAddress((void**)&KMAh, g_KMAh);  cudaGetSymbolAddress((void**)&KMAl, g_KMAl);
    cudaGetSymbolAddress((void**)&KCAh, g_KCAh);  cudaGetSymbolAddress((void**)&KCAl, g_KCAl);
    cudaGetSymbolAddress((void**)&QMAh, g_QMAh);  cudaGetSymbolAddress((void**)&QMAl, g_QMAl);
    cudaGetSymbolAddress((void**)&QCAh, g_QCAh);  cudaGetSymbolAddress((void**)&QCAl, g_QCAl);
    cudaGetSymbolAddress((void**)&VPTh, g_VPTh);  cudaGetSymbolAddress((void**)&VPTl, g_VPTl);
    cudaGetSymbolAddress((void**)&BThp, g_BTh);   cudaGetSymbolAddress((void**)&BTlp, g_BTl);
    cudaGetSymbolAddress((void**)&CVh, g_CVh);    cudaGetSymbolAddress((void**)&CVl, g_CVl);

    const int SMEM = 81920;
    cudaFuncSetAttribute(bgemm<EPI_BIAS,    OUT_PLANES  >, cudaFuncAttributeMaxDynamicSharedMemorySize, SMEM);
    cudaFuncSetAttribute(bgemm<EPI_BIAS,    OUT_PLANES_T>, cudaFuncAttributeMaxDynamicSharedMemorySize, SMEM);
    cudaFuncSetAttribute(bgemm<EPI_BIAS,    OUT_F32     >, cudaFuncAttributeMaxDynamicSharedMemorySize, SMEM);
    cudaFuncSetAttribute(bgemm<EPI_SIGMOID, OUT_F32     >, cudaFuncAttributeMaxDynamicSharedMemorySize, SMEM);
    cudaFuncSetAttribute(bgemm<EPI_SCALE,   OUT_F32     >, cudaFuncAttributeMaxDynamicSharedMemorySize, SMEM);

    const float inv_scale = 1.0f / 32.0f;
    dim3 blk(256);

    // --- preprocess: split inputs, transpose+split weights ---
    {
        int nKV = Bz * Kk * Dd, nQ = Bz * Qq * Dd;
        split_kernel<<<nKV / 1024, blk>>>(key,   KEYh, KEYl, nKV);
        split_kernel<<<nKV / 1024, blk>>>(value, VALh, VALl, nKV);
        split_kernel<<<nQ  / 1024, blk>>>(query, QRYh, QRYl, nQ);
        dim3 tg(32, 32), tb(32, 8);
        transpose_split<<<tg, tb>>>(Wk_ma, WKMAh, WKMAl);
        transpose_split<<<tg, tb>>>(Wq_ma, WQMAh, WQMAl);
        transpose_split<<<tg, tb>>>(Wk_ca, WKCAh, WKCAl);
        transpose_split<<<tg, tb>>>(Wq_ca, WQCAh, WQCAl);
        transpose_split<<<tg, tb>>>(Wv,    WVh,   WVl);
        transpose_split<<<tg, tb>>>(Wo,    WOh,   WOl);
    }

    // --- projections ---
    {
        dim3 grid(AD / 128, (Bz * Kk) / 128, 1);
        bgemm<EPI_BIAS, OUT_PLANES><<<grid, blk, SMEM>>>(
            KEYh, KEYl, WKMAh, WKMAl, bk_ma, nullptr, KMAh, KMAl,
            Bz * Kk, AD, Dd, Dd, Dd, AD,
            1, 0, 0, 0, 0, 0, 0, 1.f, nullptr, 1);
        bgemm<EPI_BIAS, OUT_PLANES><<<grid, blk, SMEM>>>(
            KEYh, KEYl, WKCAh, WKCAl, bk_ca, nullptr, KCAh, KCAl,
            Bz * Kk, AD, Dd, Dd, Dd, AD,
            1, 0, 0, 0, 0, 0, 0, 1.f, nullptr, 1);
        bgemm<EPI_BIAS, OUT_PLANES_T><<<grid, blk, SMEM>>>(
            VALh, VALl, WVh, WVl, bv, nullptr, VPTh, VPTl,
            Bz * Kk, AD, Dd, Dd, Dd, AD,
            1, 0, 0, 0, 0, 0, 0, 1.f, nullptr, Kk);
    }
    {
        dim3 grid(AD / 128, (Bz * Qq) / 128, 1);
        bgemm<EPI_BIAS, OUT_PLANES><<<grid, blk, SMEM>>>(
            QRYh, QRYl, WQMAh, WQMAl, bq_ma, nullptr, QMAh, QMAl,
            Bz * Qq, AD, Dd, Dd, Dd, AD,
            1, 0, 0, 0, 0, 0, 0, 1.f, nullptr, 1);
        bgemm<EPI_BIAS, OUT_PLANES><<<grid, blk, SMEM>>>(
            QRYh, QRYl, WQCAh, WQCAl, bq_ca, nullptr, QCAh, QCAl,
            Bz * Qq, AD, Dd, Dd, Dd, AD,
            1, 0, 0, 0, 0, 0, 0, 1.f, nullptr, 1);
    }

    // --- batched scores ---
    {
        dim3 grid((Kk + 127) / 128, Qq / 128, Bz * Hh);
        bgemm<EPI_SIGMOID, OUT_F32><<<grid, blk, SMEM>>>(
            QMAh, QMAl, KMAh, KMAl, nullptr, P, nullptr, nullptr,
            Qq, Kk, DK, AD, AD, Kk,
            Hh,
            (long long)Qq * AD, (long long)DK,
            (long long)Kk * AD, (long long)DK,
            (long long)Hh * Qq * Kk, (long long)Qq * Kk,
            inv_scale, r, 1);
        bgemm<EPI_SCALE, OUT_F32><<<grid, blk, SMEM>>>(
            QCAh, QCAl, KCAh, KCAl, nullptr, E, nullptr, nullptr,
            Qq, Kk, DK, AD, AD, Kk,
            Hh,
            (long long)Qq * AD, (long long)DK,
            (long long)Kk * AD, (long long)DK,
            (long long)Hh * Qq * Kk, (long long)Qq * Kk,
            inv_scale, nullptr, 1);
    }

    // --- cp, alpha, beta ---
    cp_kernel<<<Bz * Hh * Qq, 256>>>(P, CP);
    alpha_kernel<<<Bz * Hh, 512>>>(P, CP, aw_prev, AL);
    beta_kernel<<<Bz * Hh * Qq, 256>>>(E, AL, BThp, BTlp);

    // --- cv = beta @ v  (batched over (b,h)); output CV planes [b][q][h*DK+d] ---
    {
        dim3 grid(DK / 128, Qq / 128, Bz * Hh);
        bgemm<EPI_BIAS, OUT_PLANES><<<grid, blk, SMEM>>>(
            BThp, BTlp, VPTh, VPTl, nullptr, nullptr, CVh, CVl,
            Qq, DK, Kk, Kk, Kk, AD,
            Hh,
            (long long)Hh * Qq * Kk, (long long)Qq * Kk,
            (long long)AD * Kk, (long long)DK * Kk,
            (long long)Qq * AD, (long long)DK,
            1.f, nullptr, 1);
    }

    // --- output projection ---
    {
        dim3 grid(Dd / 128, (Bz * Qq) / 128, 1);
        bgemm<EPI_BIAS, OUT_F32><<<grid, blk, SMEM>>>(
            CVh, CVl, WOh, WOl, bo, out, nullptr, nullptr,
            Bz * Qq, Dd, AD, AD, AD, Dd,
            1, 0, 0, 0, 0, 0, 0, 1.f, nullptr, 1);
    }
}